// round 1
// baseline (speedup 1.0000x reference)
#include <cuda_runtime.h>
#include <math.h>

#define BB 8
#define RR 256
#define DD 128
#define NROW (BB*RR)
#define NEG 0.1f
#define TJ 32
#define XS 36
#define EDGE_THREADS 256

// Persistent scratch (no allocations allowed)
__device__ float g_h[NROW*DD];
__device__ float g_ti[NROW*DD];
__device__ float g_tj[NROW*DD];
__device__ float g_mpre[NROW*DD];

__device__ __forceinline__ float lrelu(float x){ return x > 0.f ? x : NEG*x; }

// ---------------------------------------------------------------------------
// K1: h = leaky(fres @ W_emb)     (2048 rows, K=20, N=128)
// ---------------------------------------------------------------------------
__global__ void k_embed(const float* __restrict__ fres, const float* __restrict__ Wemb){
    int row = blockIdx.x, c = threadIdx.x;
    __shared__ float sf[20];
    if (c < 20) sf[c] = fres[row*20 + c];
    __syncthreads();
    float acc = 0.f;
    #pragma unroll
    for (int k = 0; k < 20; k++) acc += sf[k]*Wemb[k*DD + c];
    g_h[(size_t)row*DD + c] = lrelu(acc);
}

// ---------------------------------------------------------------------------
// K3: ti = h @ W_i + b_e1 ; tj = h @ W_j        (W_e1 rows 0..127 / 128..255)
// ---------------------------------------------------------------------------
__global__ void k_titj(const float* __restrict__ We1, const float* __restrict__ be1){
    int row = blockIdx.x, c = threadIdx.x;
    __shared__ float sh[DD];
    sh[c] = g_h[(size_t)row*DD + c];
    __syncthreads();
    float ai = be1[c], aj = 0.f;
    #pragma unroll 8
    for (int k = 0; k < DD; k++){
        float hk = sh[k];
        ai += hk * We1[k*DD + c];
        aj += hk * We1[(DD + k)*DD + c];
    }
    g_ti[(size_t)row*DD + c] = ai;
    g_tj[(size_t)row*DD + c] = aj;
}

// ---------------------------------------------------------------------------
// K4: edge kernel (the 98% kernel).
// One block per (b,i). For each 32-j tile:
//   X[k][j] = leaky(ti[k] + tj[j][k] + d2(i,j)*w_d[k])       (in SMEM, transposed)
//   M = X^T @ W_e2  (32x128, 4x4 register blocking, W_e2 in SMEM)
//   m = leaky(M + b_e2); e = sigmoid(m . W_inf + b_inf) * (j != i)
//   m_pre[c] += m*e   (warp shuffles + shared atomics across warps)
// ---------------------------------------------------------------------------
__global__ void __launch_bounds__(EDGE_THREADS, 2)
k_edge(const float* __restrict__ We2,
       const float* __restrict__ be2,
       const float* __restrict__ Winf,
       const float* __restrict__ binf,
       const float* __restrict__ We1,
       const float* __restrict__ coords)
{
    extern __shared__ float smem[];
    float* sW  = smem;               // 128*128
    float* sX  = sW  + DD*DD;        // 128*XS (transposed: [k][j], stride 36)
    float* sti = sX  + DD*XS;        // 128
    float* sC  = sti + DD;           // 3*256 (x | y | z)
    float* sMp = sC  + 3*RR;         // 128

    const int t  = threadIdx.x;
    const int bx = blockIdx.x;
    const int b  = bx >> 8;
    const int i  = bx & 255;

    // stage W_e2 (row-major [k][c]), ti row, coords, zero m_pre accumulator
    for (int idx = t*4; idx < DD*DD; idx += EDGE_THREADS*4)
        *(float4*)&sW[idx] = *(const float4*)&We2[idx];
    if (t < DD) { sti[t] = g_ti[(size_t)bx*DD + t]; sMp[t] = 0.f; }
    if (t < RR) {
        const float* cp = coords + ((size_t)b*RR + t)*3;
        sC[t] = cp[0]; sC[RR + t] = cp[1]; sC[2*RR + t] = cp[2];
    }
    __syncthreads();

    // X-build role: thread covers fixed k, half the j's
    const int   k   = t & 127;
    const int   jh  = t >> 7;
    const float tiv = sti[k];
    const float wdk = We1[256*DD + k];           // w_d
    const float cix = sC[i], ciy = sC[RR + i], ciz = sC[2*RR + i];

    // GEMM role: warp w owns j = j0 + 4w .. +3 ; lane owns c = 4*lane .. +3
    const int w    = t >> 5;
    const int lane = t & 31;
    const float4 be2v = *(const float4*)&be2[lane*4];
    const float4 wfv  = *(const float4*)&Winf[lane*4];
    const float  bi   = binf[0];

    float mp0 = 0.f, mp1 = 0.f, mp2 = 0.f, mp3 = 0.f;

    for (int j0 = 0; j0 < RR; j0 += TJ) {
        // ---- build leaky(pre) tile, transposed ----
        #pragma unroll
        for (int jj = jh; jj < TJ; jj += 2) {
            int j = j0 + jj;
            float dx = sC[j] - cix, dy = sC[RR + j] - ciy, dz = sC[2*RR + j] - ciz;
            float d2 = dx*dx + dy*dy + dz*dz;
            float tjv = g_tj[((size_t)(b*RR + j))*DD + k];
            sX[k*XS + jj] = lrelu(tiv + tjv + d2*wdk);
        }
        __syncthreads();

        // ---- 32x128 = (32x128) @ (128x128) ----
        float acc[4][4];
        #pragma unroll
        for (int a = 0; a < 4; a++)
            #pragma unroll
            for (int q = 0; q < 4; q++) acc[a][q] = 0.f;

        const float* xrow = sX + (w << 2);
        const float* wrow = sW + (lane << 2);
        #pragma unroll 4
        for (int kk = 0; kk < DD; kk++) {
            float4 xv = *(const float4*)(xrow + kk*XS);   // broadcast (4 j's)
            float4 wv = *(const float4*)(wrow + kk*DD);   // 4 c's
            acc[0][0] += xv.x*wv.x; acc[0][1] += xv.x*wv.y; acc[0][2] += xv.x*wv.z; acc[0][3] += xv.x*wv.w;
            acc[1][0] += xv.y*wv.x; acc[1][1] += xv.y*wv.y; acc[1][2] += xv.y*wv.z; acc[1][3] += xv.y*wv.w;
            acc[2][0] += xv.z*wv.x; acc[2][1] += xv.z*wv.y; acc[2][2] += xv.z*wv.z; acc[2][3] += xv.z*wv.w;
            acc[3][0] += xv.w*wv.x; acc[3][1] += xv.w*wv.y; acc[3][2] += xv.w*wv.z; acc[3][3] += xv.w*wv.w;
        }

        // ---- epilogue: gate + masked reduction over j ----
        #pragma unroll
        for (int jq = 0; jq < 4; jq++) {
            float m0 = lrelu(acc[jq][0] + be2v.x);
            float m1 = lrelu(acc[jq][1] + be2v.y);
            float m2 = lrelu(acc[jq][2] + be2v.z);
            float m3 = lrelu(acc[jq][3] + be2v.w);
            float ep = m0*wfv.x + m1*wfv.y + m2*wfv.z + m3*wfv.w;
            ep += __shfl_xor_sync(0xffffffffu, ep, 16);
            ep += __shfl_xor_sync(0xffffffffu, ep, 8);
            ep += __shfl_xor_sync(0xffffffffu, ep, 4);
            ep += __shfl_xor_sync(0xffffffffu, ep, 2);
            ep += __shfl_xor_sync(0xffffffffu, ep, 1);
            int j = j0 + (w << 2) + jq;
            float e = (j == i) ? 0.f : 1.f/(1.f + expf(-(ep + bi)));
            mp0 += m0*e; mp1 += m1*e; mp2 += m2*e; mp3 += m3*e;
        }
        __syncthreads();   // protect sX before next tile's writes
    }

    // cross-warp reduction of m_pre
    const int c0 = lane*4;
    atomicAdd(&sMp[c0+0], mp0);
    atomicAdd(&sMp[c0+1], mp1);
    atomicAdd(&sMp[c0+2], mp2);
    atomicAdd(&sMp[c0+3], mp3);
    __syncthreads();
    if (t < DD) g_mpre[(size_t)bx*DD + t] = sMp[t];
}

// ---------------------------------------------------------------------------
// K5: h = leaky([h, m_pre] @ W_h1 + b_h1) @ W_h2 + b_h2 + h
// ---------------------------------------------------------------------------
__global__ void k_update(const float* __restrict__ Wh1, const float* __restrict__ bh1,
                         const float* __restrict__ Wh2, const float* __restrict__ bh2,
                         float* __restrict__ out)
{
    int row = blockIdx.x, c = threadIdx.x;
    __shared__ float shm[2*DD];
    __shared__ float su[DD];
    float hold = g_h[(size_t)row*DD + c];
    shm[c]      = hold;
    shm[DD + c] = g_mpre[(size_t)row*DD + c];
    __syncthreads();
    float acc = bh1[c];
    #pragma unroll 8
    for (int kk = 0; kk < 2*DD; kk++) acc += shm[kk]*Wh1[kk*DD + c];
    su[c] = lrelu(acc);
    __syncthreads();
    float a2 = bh2[c];
    #pragma unroll 8
    for (int kk = 0; kk < DD; kk++) a2 += su[kk]*Wh2[kk*DD + c];
    float hn = a2 + hold;
    g_h[(size_t)row*DD + c] = hn;
    if (out) out[(size_t)row*DD + c] = hn;
}

// ---------------------------------------------------------------------------
extern "C" void kernel_launch(void* const* d_in, const int* in_sizes, int n_in,
                              void* d_out, int out_size)
{
    const float* fres   = (const float*)d_in[0];
    const float* coords = (const float*)d_in[1];
    const float* Wemb   = (const float*)d_in[2];
    const float* We1    = (const float*)d_in[3];
    const float* be1    = (const float*)d_in[4];
    const float* We2    = (const float*)d_in[5];
    const float* be2    = (const float*)d_in[6];
    const float* Winf   = (const float*)d_in[7];
    const float* binf   = (const float*)d_in[8];
    const float* Wh1    = (const float*)d_in[9];
    const float* bh1    = (const float*)d_in[10];
    const float* Wh2    = (const float*)d_in[11];
    const float* bh2    = (const float*)d_in[12];
    float* out = (float*)d_out;

    const size_t EDGE_SMEM = (size_t)(DD*DD + DD*XS + DD + 3*RR + DD)*sizeof(float);
    cudaFuncSetAttribute(k_edge, cudaFuncAttributeMaxDynamicSharedMemorySize,
                         (int)EDGE_SMEM);

    k_embed<<<NROW, DD>>>(fres, Wemb);
    for (int it = 0; it < 2; it++) {
        k_titj<<<NROW, DD>>>(We1, be1);
        k_edge<<<NROW, EDGE_THREADS, EDGE_SMEM>>>(We2, be2, Winf, binf, We1, coords);
        k_update<<<NROW, DD>>>(Wh1, bh1, Wh2, bh2, (it == 1) ? out : nullptr);
    }
}

// round 3
// speedup vs baseline: 2.9341x; 2.9341x over previous
#include <cuda_runtime.h>
#include <cstdint>
#include <math.h>

#define BB 8
#define RR 256
#define DD 128
#define NROW (BB*RR)
#define NEG 0.1f
#define SXW 132            // X row stride (words): %32 == 4  -> conflict-free A frags
#define SWW 136            // W row stride (words): %32 == 8  -> conflict-free B frags

// Persistent scratch (no allocations allowed)
__device__ float g_h[NROW*DD];
__device__ float g_ti[NROW*DD];
__device__ float g_tj[NROW*DD];
__device__ float g_mpre[NROW*DD];

__device__ __forceinline__ float lrelu(float x){ return x > 0.f ? x : NEG*x; }

__device__ __forceinline__ float rna_tf32(float x){
    uint32_t u;
    asm("cvt.rna.tf32.f32 %0, %1;" : "=r"(u) : "f"(x));
    return __uint_as_float(u);
}

// ---------------------------------------------------------------------------
// K1: h = leaky(fres @ W_emb)
// ---------------------------------------------------------------------------
__global__ void k_embed(const float* __restrict__ fres, const float* __restrict__ Wemb){
    int row = blockIdx.x, c = threadIdx.x;
    __shared__ float sf[20];
    if (c < 20) sf[c] = fres[row*20 + c];
    __syncthreads();
    float acc = 0.f;
    #pragma unroll
    for (int k = 0; k < 20; k++) acc += sf[k]*Wemb[k*DD + c];
    g_h[(size_t)row*DD + c] = lrelu(acc);
}

// ---------------------------------------------------------------------------
// K3: ti = h @ W_i + b_e1 ; tj = h @ W_j
// ---------------------------------------------------------------------------
__global__ void k_titj(const float* __restrict__ We1, const float* __restrict__ be1){
    int row = blockIdx.x; int t = threadIdx.x;
    int c = t & 127, which = t >> 7;
    __shared__ float sh[DD];
    if (t < DD) sh[t] = g_h[(size_t)row*DD + t];
    __syncthreads();
    const float* W = We1 + which*DD*DD;
    float a0=0.f, a1=0.f, a2=0.f, a3=0.f;
    #pragma unroll 4
    for (int k = 0; k < DD; k += 4){
        a0 += sh[k+0]*W[(k+0)*DD + c];
        a1 += sh[k+1]*W[(k+1)*DD + c];
        a2 += sh[k+2]*W[(k+2)*DD + c];
        a3 += sh[k+3]*W[(k+3)*DD + c];
    }
    float r = (a0+a1)+(a2+a3);
    if (which == 0) g_ti[(size_t)row*DD + c] = r + be1[c];
    else            g_tj[(size_t)row*DD + c] = r;
}

// ---------------------------------------------------------------------------
// K4: edge kernel — tf32 mma.sync (base ISA, works on family target sm_103).
// Persistent grid=148, 1 CTA/SM, 8 warps = 4(j) x 2(c), warp tile 64x64.
// OUT[j][c] = X[j][:] . W[:,c] ; X = leaky(ti + tj + d2*wd) rounded to tf32.
// Epilogue fuses m=lrelu(OUT+b), e=sigmoid(m.Winf+bi)*mask, mpre=sum_j m*e.
// ---------------------------------------------------------------------------
__global__ void __launch_bounds__(256, 1)
k_edge(const float* __restrict__ be2,
       const float* __restrict__ Winf,
       const float* __restrict__ binf,
       const float* __restrict__ We1,
       const float* __restrict__ We2,
       const float* __restrict__ coords,
       int ntiles)
{
    extern __shared__ float sm[];
    float* sW  = sm;                    // 128*SWW
    float* sX  = sW  + DD*SWW;          // 256*SXW
    float* sC  = sX  + RR*SXW;          // 3*256
    float* sD2 = sC  + 3*RR;            // 256
    float* sEp = sD2 + RR;              // 256
    float* sE  = sEp + RR;              // 256
    float* sTi = sE  + RR;              // 128
    float* sWd = sTi + DD;              // 128
    float* sMp = sWd + DD;              // 128
    float* sBc = sMp + DD;              // 128
    float* sWc = sBc + DD;              // 128

    const int t    = threadIdx.x;
    const int w    = t >> 5;
    const int lane = t & 31;
    const int g    = lane >> 2;         // 0..7
    const int tig  = lane & 3;          // 0..3
    const int jbase = (w >> 1) * 64;
    const int cbase = (w & 1) * 64;

    // one-time staging: rounded W_e2, w_d, biases
    for (int idx = t; idx < DD*DD; idx += 256) {
        int k = idx >> 7, c = idx & 127;
        sW[k*SWW + c] = rna_tf32(We2[idx]);
    }
    if (t < DD) {
        sWd[t] = We1[2*DD*DD + t];
        sBc[t] = be2[t];
        sWc[t] = Winf[t];
    }
    const float bi = binf[0];
    __syncthreads();

    for (int tile = blockIdx.x; tile < ntiles; tile += gridDim.x) {
        const int b = tile >> 8, i = tile & 255;

        // ---- per-tile staging ----
        {
            const float* cp = coords + ((size_t)b*RR + t)*3;
            sC[t] = cp[0]; sC[RR + t] = cp[1]; sC[2*RR + t] = cp[2];
        }
        if (t < DD) { sTi[t] = g_ti[(size_t)tile*DD + t]; sMp[t] = 0.f; }
        sEp[t] = 0.f;
        __syncthreads();
        {
            float dx = sC[t] - sC[i], dy = sC[RR+t] - sC[RR+i], dz = sC[2*RR+t] - sC[2*RR+i];
            sD2[t] = dx*dx + dy*dy + dz*dz;
        }
        __syncthreads();

        // ---- build X (warp per j row, lane per k-quad), tf32-rounded ----
        {
            const float* tjb = g_tj + (size_t)b*RR*DD;
            const int k4 = lane*4;
            const float ti0 = sTi[k4], ti1 = sTi[k4+1], ti2 = sTi[k4+2], ti3 = sTi[k4+3];
            const float wd0 = sWd[k4], wd1 = sWd[k4+1], wd2 = sWd[k4+2], wd3 = sWd[k4+3];
            for (int j = w; j < RR; j += 8) {
                float4 tv = *(const float4*)&tjb[(size_t)j*DD + k4];
                float d2 = sD2[j];
                float x0 = rna_tf32(lrelu(ti0 + tv.x + d2*wd0));
                float x1 = rna_tf32(lrelu(ti1 + tv.y + d2*wd1));
                float x2 = rna_tf32(lrelu(ti2 + tv.z + d2*wd2));
                float x3 = rna_tf32(lrelu(ti3 + tv.w + d2*wd3));
                *(float4*)&sX[j*SXW + k4] = make_float4(x0, x1, x2, x3);
            }
        }
        __syncthreads();

        // ---- mainloop: 64x64 warp tile, m16n8k8 tf32 ----
        float acc[4][8][4];
        #pragma unroll
        for (int mi = 0; mi < 4; mi++)
            #pragma unroll
            for (int ni = 0; ni < 8; ni++)
                #pragma unroll
                for (int q = 0; q < 4; q++) acc[mi][ni][q] = 0.f;

        #pragma unroll 4
        for (int k0 = 0; k0 < DD; k0 += 8) {
            uint32_t A[4][4];
            #pragma unroll
            for (int mi = 0; mi < 4; mi++) {
                const float* xr = sX + (jbase + mi*16 + g)*SXW + k0 + tig;
                A[mi][0] = __float_as_uint(xr[0]);
                A[mi][1] = __float_as_uint(xr[8*SXW]);
                A[mi][2] = __float_as_uint(xr[4]);
                A[mi][3] = __float_as_uint(xr[8*SXW + 4]);
            }
            uint32_t Bf[8][2];
            #pragma unroll
            for (int ni = 0; ni < 8; ni++) {
                const float* wr = sW + (k0 + tig)*SWW + cbase + ni*8 + g;
                Bf[ni][0] = __float_as_uint(wr[0]);
                Bf[ni][1] = __float_as_uint(wr[4*SWW]);
            }
            #pragma unroll
            for (int mi = 0; mi < 4; mi++)
                #pragma unroll
                for (int ni = 0; ni < 8; ni++)
                    asm volatile(
                        "mma.sync.aligned.m16n8k8.row.col.f32.tf32.tf32.f32 "
                        "{%0,%1,%2,%3}, {%4,%5,%6,%7}, {%8,%9}, {%0,%1,%2,%3};"
                        : "+f"(acc[mi][ni][0]), "+f"(acc[mi][ni][1]),
                          "+f"(acc[mi][ni][2]), "+f"(acc[mi][ni][3])
                        : "r"(A[mi][0]), "r"(A[mi][1]), "r"(A[mi][2]), "r"(A[mi][3]),
                          "r"(Bf[ni][0]), "r"(Bf[ni][1]));
        }

        // ---- epilogue ----
        float bc[16], wc[16];
        #pragma unroll
        for (int ni = 0; ni < 8; ni++)
            #pragma unroll
            for (int q = 0; q < 2; q++) {
                int c = cbase + ni*8 + tig*2 + q;
                bc[ni*2+q] = sBc[c];
                wc[ni*2+q] = sWc[c];
            }

        // pass 1: per-j gate logit partials
        #pragma unroll
        for (int mi = 0; mi < 4; mi++)
            #pragma unroll
            for (int r = 0; r < 2; r++) {
                float p = 0.f;
                #pragma unroll
                for (int ni = 0; ni < 8; ni++)
                    #pragma unroll
                    for (int q = 0; q < 2; q++)
                        p += lrelu(acc[mi][ni][r*2+q] + bc[ni*2+q]) * wc[ni*2+q];
                p += __shfl_xor_sync(0xffffffffu, p, 1);
                p += __shfl_xor_sync(0xffffffffu, p, 2);
                if (tig == 0) atomicAdd(&sEp[jbase + mi*16 + g + r*8], p);
            }
        __syncthreads();
        {
            float s = sEp[t] + bi;
            sE[t] = (t == i) ? 0.f : __fdividef(1.f, 1.f + __expf(-s));
        }
        __syncthreads();

        // pass 2: mpre[c] = sum_j m*e
        float macc[16];
        #pragma unroll
        for (int q = 0; q < 16; q++) macc[q] = 0.f;
        #pragma unroll
        for (int mi = 0; mi < 4; mi++)
            #pragma unroll
            for (int r = 0; r < 2; r++) {
                float e = sE[jbase + mi*16 + g + r*8];
                #pragma unroll
                for (int ni = 0; ni < 8; ni++)
                    #pragma unroll
                    for (int q = 0; q < 2; q++)
                        macc[ni*2+q] += lrelu(acc[mi][ni][r*2+q] + bc[ni*2+q]) * e;
            }
        #pragma unroll
        for (int q = 0; q < 16; q++) {
            macc[q] += __shfl_xor_sync(0xffffffffu, macc[q], 4);
            macc[q] += __shfl_xor_sync(0xffffffffu, macc[q], 8);
            macc[q] += __shfl_xor_sync(0xffffffffu, macc[q], 16);
        }
        if (g == 0) {
            #pragma unroll
            for (int q = 0; q < 16; q++)
                atomicAdd(&sMp[cbase + (q >> 1)*8 + tig*2 + (q & 1)], macc[q]);
        }
        __syncthreads();
        if (t < DD) g_mpre[(size_t)tile*DD + t] = sMp[t];
        __syncthreads();
    }
}

// ---------------------------------------------------------------------------
// K5: h = leaky([h, m_pre] @ W_h1 + b_h1) @ W_h2 + b_h2 + h
// ---------------------------------------------------------------------------
__global__ void k_update(const float* __restrict__ Wh1, const float* __restrict__ bh1,
                         const float* __restrict__ Wh2, const float* __restrict__ bh2,
                         float* __restrict__ out)
{
    int row = blockIdx.x, c = threadIdx.x;
    __shared__ float shm[2*DD];
    __shared__ float su[DD];
    float hold = g_h[(size_t)row*DD + c];
    shm[c]      = hold;
    shm[DD + c] = g_mpre[(size_t)row*DD + c];
    __syncthreads();
    float a0 = 0.f, a1 = 0.f, a2 = 0.f, a3 = 0.f;
    #pragma unroll 4
    for (int k = 0; k < 2*DD; k += 4){
        a0 += shm[k+0]*Wh1[(k+0)*DD + c];
        a1 += shm[k+1]*Wh1[(k+1)*DD + c];
        a2 += shm[k+2]*Wh1[(k+2)*DD + c];
        a3 += shm[k+3]*Wh1[(k+3)*DD + c];
    }
    su[c] = lrelu((a0+a1)+(a2+a3) + bh1[c]);
    __syncthreads();
    float b0 = 0.f, b1 = 0.f, b2 = 0.f, b3 = 0.f;
    #pragma unroll 4
    for (int k = 0; k < DD; k += 4){
        b0 += su[k+0]*Wh2[(k+0)*DD + c];
        b1 += su[k+1]*Wh2[(k+1)*DD + c];
        b2 += su[k+2]*Wh2[(k+2)*DD + c];
        b3 += su[k+3]*Wh2[(k+3)*DD + c];
    }
    float hn = (b0+b1)+(b2+b3) + bh2[c] + hold;
    g_h[(size_t)row*DD + c] = hn;
    if (out) out[(size_t)row*DD + c] = hn;
}

// ---------------------------------------------------------------------------
extern "C" void kernel_launch(void* const* d_in, const int* in_sizes, int n_in,
                              void* d_out, int out_size)
{
    const float* fres   = (const float*)d_in[0];
    const float* coords = (const float*)d_in[1];
    const float* Wemb   = (const float*)d_in[2];
    const float* We1    = (const float*)d_in[3];
    const float* be1    = (const float*)d_in[4];
    const float* We2    = (const float*)d_in[5];
    const float* be2    = (const float*)d_in[6];
    const float* Winf   = (const float*)d_in[7];
    const float* binf   = (const float*)d_in[8];
    const float* Wh1    = (const float*)d_in[9];
    const float* bh1    = (const float*)d_in[10];
    const float* Wh2    = (const float*)d_in[11];
    const float* bh2    = (const float*)d_in[12];
    float* out = (float*)d_out;

    const int EDGE_SMEM = (DD*SWW + RR*SXW + 3*RR + RR + RR + RR + DD + DD + DD + DD + DD)
                          * (int)sizeof(float);
    cudaFuncSetAttribute(k_edge, cudaFuncAttributeMaxDynamicSharedMemorySize, EDGE_SMEM);

    k_embed<<<NROW, DD>>>(fres, Wemb);
    for (int it = 0; it < 2; it++) {
        k_titj<<<NROW, 2*DD>>>(We1, be1);
        k_edge<<<148, 256, EDGE_SMEM>>>(be2, Winf, binf, We1, We2, coords, NROW);
        k_update<<<NROW, DD>>>(Wh1, bh1, Wh2, bh2, (it == 1) ? out : nullptr);
    }
}